// round 13
// baseline (speedup 1.0000x reference)
#include <cuda_runtime.h>
#include <cuda_fp16.h>
#include <math.h>
#include <stdint.h>

// ---------------- problem constants ----------------
#define B_  32
#define C_  3
#define IMG_ 224
#define P_  16
#define W_  768
#define L_  12
#define H_  12
#define S_  197
#define HD_ 64
#define FF_ 3072
#define E_  512
#define NPATCH_ 196
#define BSW_ (B_*S_*W_)
#define SKP_ 224
#define QKV_ 2304

// ---------------- scratch ----------------
__device__ float  g_h   [BSW_];
__device__ __half g_y   [BSW_];
__device__ __half g_qh  [BSW_];
__device__ __half g_kh  [BSW_];
__device__ __half g_vh  [BSW_];
__device__ __half g_o   [BSW_];
__device__ __half g_ff  [B_*S_*FF_];
__device__ __half g_im2col[B_*NPATCH_*W_];
__device__ float  g_tok [B_*NPATCH_*W_];
__device__ __half g_cls [B_*W_];
__device__ __half g_convw16[W_*W_];
__device__ __half g_wqkvT[L_*QKV_*W_];
__device__ float  g_bqkv [L_*QKV_];
__device__ __half g_woT [L_*W_*W_];
__device__ __half g_w1T [L_*W_*FF_];
__device__ __half g_w2T [L_*FF_*W_];
__device__ __half g_projT[W_*E_];

__device__ __forceinline__ float gelu_exact(float v) {
    return 0.5f * v * (1.0f + erff(v * 0.70710678118654752f));
}
__device__ __forceinline__ uint32_t smem_u32(const void* p) {
    uint32_t a;
    asm("{ .reg .u64 t; cvta.to.shared.u64 t, %1; cvt.u32.u64 %0, t; }" : "=r"(a) : "l"(p));
    return a;
}

#define LDSM_X4(r, addr) \
    asm volatile("ldmatrix.sync.aligned.m8n8.x4.shared.b16 {%0,%1,%2,%3}, [%4];" \
        : "=r"((r)[0]), "=r"((r)[1]), "=r"((r)[2]), "=r"((r)[3]) : "r"(addr))
#define LDSM_X2(r, addr) \
    asm volatile("ldmatrix.sync.aligned.m8n8.x2.shared.b16 {%0,%1}, [%2];" \
        : "=r"((r)[0]), "=r"((r)[1]) : "r"(addr))
#define LDSM_X2T(r, addr) \
    asm volatile("ldmatrix.sync.aligned.m8n8.x2.trans.shared.b16 {%0,%1}, [%2];" \
        : "=r"((r)[0]), "=r"((r)[1]) : "r"(addr))

__device__ __forceinline__ void cp16(uint32_t dst, const void* src, bool valid) {
    int sz = valid ? 16 : 0;
    asm volatile("cp.async.cg.shared.global [%0], [%1], 16, %2;"
                 :: "r"(dst), "l"(src), "r"(sz));
}
#define CP_COMMIT() asm volatile("cp.async.commit_group;" ::: "memory")
#define CP_WAIT1()  asm volatile("cp.async.wait_group 1;" ::: "memory")
#define CP_WAIT2()  asm volatile("cp.async.wait_group 2;" ::: "memory")
#define CP_WAIT0()  asm volatile("cp.async.wait_group 0;" ::: "memory")

#define MMA16816(acc, af, bf) \
    asm volatile("mma.sync.aligned.m16n8k16.row.col.f32.f16.f16.f32 " \
        "{%0,%1,%2,%3}, {%4,%5,%6,%7}, {%8,%9}, {%0,%1,%2,%3};" \
        : "+f"((acc)[0]), "+f"((acc)[1]), "+f"((acc)[2]), "+f"((acc)[3]) \
        : "r"((af)[0]), "r"((af)[1]), "r"((af)[2]), "r"((af)[3]), \
          "r"((bf)[0]), "r"((bf)[1]))

// =====================================================================
// WIDE GEMM: 128x256 CTA tile, 512 threads (16 warps x 64x32), KT=64,
// 3-stage cp.async (166KB smem, 1 CTA/SM). Half the barriers of KT=32.
// OUT_MODE: 0 = f32 C (opt ACCUM/bias), 1 = f16 Ch (opt gelu), 3 = QKV route.
// Requires K % 64 == 0 and K >= 192 (all call sites: K=768).
// =====================================================================
#define WSTR 144
#define ASTG (128 * WSTR)                 // 18432
#define BSTG (256 * WSTR)                 // 36864
#define WSMEM (3 * (ASTG + BSTG))         // 165888

template<int HAS_BIAS, int ACCUM, int DO_GELU, int OUT_MODE>
__global__ __launch_bounds__(512)
void gemm_wide(const __half* __restrict__ A, const __half* __restrict__ Bt,
               const float* __restrict__ bias, float* __restrict__ C,
               __half* __restrict__ Ch, __half* __restrict__ Kh,
               __half* __restrict__ Vh,
               int M, int N, int K, int lda, int ldb, int ldc)
{
    extern __shared__ __align__(128) uint8_t sm[];
    uint8_t* smA = sm;
    uint8_t* smB = sm + 3 * ASTG;

    const int t    = threadIdx.x;
    const int warp = t >> 5, lane = t & 31;
    const int m0   = blockIdx.y * 128;
    const int n0   = blockIdx.x * 256;
    const int wm   = (warp >> 3) * 64;
    const int wn   = (warp & 7) * 32;
    const int grp  = lane >> 2;
    const int idx  = lane & 3;

    float acc[4][4][4];
    #pragma unroll
    for (int a = 0; a < 4; a++)
        #pragma unroll
        for (int b = 0; b < 4; b++)
            #pragma unroll
            for (int c = 0; c < 4; c++) acc[a][b][c] = 0.0f;

    const uint32_t saA = smem_u32(smA);
    const uint32_t saB = smem_u32(smB);

    // cp.async mapping (512 thr), KT=64 (128B rows):
    // A: 128 rows x 8 chunks = 1024 -> 2/thr ; B: 256 rows x 8 = 2048 -> 4/thr
    const int rowA = t >> 2;            // 0..127
    const int ckA  = (t & 3) * 2;       // 16B-chunk {0,2,4,6}
    const int rowB = t >> 1;            // 0..255
    const int ckB  = (t & 1) * 4;       // {0,4}

    const bool aValid = (m0 + rowA) < M;
    const bool bValid = (n0 + rowB) < N;
    const __half* aBase = A  + (size_t)(m0 + rowA) * lda + ckA * 8;
    const __half* bBase = Bt + (size_t)(n0 + rowB) * ldb + ckB * 8;
    const uint32_t dA = saA + rowA * WSTR + ckA * 16;
    const uint32_t dB = saB + rowB * WSTR + ckB * 16;

    const int nk = K / 64;

    auto load_stage = [&](int kt, int buf) {
        const bool ok = kt < nk;
        const int ko = ok ? kt * 64 : 0;
        cp16(dA + buf * ASTG,      aBase + ko,      ok && aValid);
        cp16(dA + buf * ASTG + 16, aBase + ko + 8,  ok && aValid);
        cp16(dB + buf * BSTG,      bBase + ko,      ok && bValid);
        cp16(dB + buf * BSTG + 16, bBase + ko + 8,  ok && bValid);
        cp16(dB + buf * BSTG + 32, bBase + ko + 16, ok && bValid);
        cp16(dB + buf * BSTG + 48, bBase + ko + 24, ok && bValid);
    };

    const int aoff = (wm + (lane & 15)) * WSTR + (lane >> 4) * 16;
    const int boff = (wn + (lane & 7))  * WSTR + ((lane >> 3) & 1) * 16;

    auto compute = [&](int buf) {
        const uint32_t sa = saA + buf * ASTG;
        const uint32_t sb = saB + buf * BSTG;
        #pragma unroll
        for (int ks = 0; ks < 4; ks++) {
            uint32_t af[4][4], bf[4][2];
            #pragma unroll
            for (int mt = 0; mt < 4; mt++)
                LDSM_X4(af[mt], sa + aoff + mt * 16 * WSTR + ks * 32);
            #pragma unroll
            for (int nt = 0; nt < 4; nt++)
                LDSM_X2(bf[nt], sb + boff + nt * 8 * WSTR + ks * 32);
            #pragma unroll
            for (int mt = 0; mt < 4; mt++)
                #pragma unroll
                for (int nt = 0; nt < 4; nt++)
                    MMA16816(acc[mt][nt], af[mt], bf[nt]);
        }
    };

    load_stage(0, 0); CP_COMMIT();
    load_stage(1, 1); CP_COMMIT();

    int buf = 0, nbuf = 2;
    for (int kt = 0; kt < nk; kt++) {
        CP_WAIT1();
        __syncthreads();
        load_stage(kt + 2, nbuf);
        CP_COMMIT();
        compute(buf);
        buf = (buf == 2) ? 0 : buf + 1;
        nbuf = (nbuf == 2) ? 0 : nbuf + 1;
    }

    #pragma unroll
    for (int mt = 0; mt < 4; mt++) {
        const int r0 = m0 + wm + mt * 16 + grp;
        #pragma unroll
        for (int half = 0; half < 2; half++) {
            const int gm = r0 + half * 8;
            if (gm >= M) continue;
            #pragma unroll
            for (int nt = 0; nt < 4; nt++) {
                const int gn = n0 + wn + nt * 8 + idx * 2;
                if (gn >= N) continue;
                float v0 = acc[mt][nt][half * 2 + 0];
                float v1 = acc[mt][nt][half * 2 + 1];
                if (HAS_BIAS) { v0 += bias[gn]; v1 += bias[gn + 1]; }
                if (DO_GELU)  { v0 = gelu_exact(v0); v1 = gelu_exact(v1); }
                if (OUT_MODE == 3) {
                    __half2 hv = __floats2half2_rn(v0, v1);
                    if (gn < W_)
                        *reinterpret_cast<__half2*>(Ch + (size_t)gm * W_ + gn) = hv;
                    else if (gn < 2 * W_)
                        *reinterpret_cast<__half2*>(Kh + (size_t)gm * W_ + gn - W_) = hv;
                    else
                        *reinterpret_cast<__half2*>(Vh + (size_t)gm * W_ + gn - 2 * W_) = hv;
                } else if (OUT_MODE == 1) {
                    *reinterpret_cast<__half2*>(Ch + (size_t)gm * ldc + gn) =
                        __floats2half2_rn(v0, v1);
                } else {
                    float* p = C + (size_t)gm * ldc + gn;
                    if (ACCUM) {
                        float2 old = *reinterpret_cast<float2*>(p);
                        v0 += old.x; v1 += old.y;
                    }
                    *reinterpret_cast<float2*>(p) = make_float2(v0, v1);
                }
            }
        }
    }
}

// =====================================================================
// NARROW GEMM: 128x128 tile, 256 threads, 2 CTAs/SM (N=768 GEMMs).
// =====================================================================
#define STRIDE 80
#define STAGEB (128 * STRIDE)
#define NSMEM (8 * STAGEB)   // 81920

template<int HAS_BIAS, int ACCUM>
__global__ __launch_bounds__(256, 2)
void gemm_n(const __half* __restrict__ A, const __half* __restrict__ Bt,
            const float* __restrict__ bias, float* __restrict__ C,
            int M, int N, int K, int lda, int ldb, int ldc)
{
    extern __shared__ __align__(128) uint8_t sm[];
    uint8_t* smA = sm;
    uint8_t* smB = sm + 4 * STAGEB;

    const int t    = threadIdx.x;
    const int warp = t >> 5, lane = t & 31;
    const int m0   = blockIdx.y * 128;
    const int n0   = blockIdx.x * 128;
    const int wm   = (warp >> 2) * 64;
    const int wn   = (warp & 3) * 32;
    const int grp  = lane >> 2;
    const int idx  = lane & 3;

    float acc[4][4][4];
    #pragma unroll
    for (int a = 0; a < 4; a++)
        #pragma unroll
        for (int b = 0; b < 4; b++)
            #pragma unroll
            for (int c = 0; c < 4; c++) acc[a][b][c] = 0.0f;

    const uint32_t saA = smem_u32(smA);
    const uint32_t saB = smem_u32(smB);

    const int rowL = t >> 1;
    const int ck0  = (t & 1) * 2;
    const bool aValid = (m0 + rowL) < M;
    const bool bValid = (n0 + rowL) < N;
    const __half* aBase = A + (size_t)(m0 + rowL) * lda + ck0 * 8;
    const __half* bBase = Bt + (size_t)(n0 + rowL) * ldb + ck0 * 8;
    const uint32_t dA = saA + rowL * STRIDE + ck0 * 16;
    const uint32_t dB = saB + rowL * STRIDE + ck0 * 16;

    const int nk = K / 32;

    auto load_stage = [&](int kt, int buf) {
        const bool ok = kt < nk;
        const int ko = ok ? kt * 32 : 0;
        cp16(dA + buf * STAGEB,      aBase + ko,     ok && aValid);
        cp16(dA + buf * STAGEB + 16, aBase + ko + 8, ok && aValid);
        cp16(dB + buf * STAGEB,      bBase + ko,     ok && bValid);
        cp16(dB + buf * STAGEB + 16, bBase + ko + 8, ok && bValid);
    };

    const int aoff = (wm + (lane & 15)) * STRIDE + (lane >> 4) * 16;
    const int boff = (wn + (lane & 7))  * STRIDE + ((lane >> 3) & 1) * 16;

    auto compute = [&](int buf) {
        const uint32_t sa = saA + buf * STAGEB;
        const uint32_t sb = saB + buf * STAGEB;
        #pragma unroll
        for (int ks = 0; ks < 2; ks++) {
            uint32_t af[4][4], bf[4][2];
            #pragma unroll
            for (int mt = 0; mt < 4; mt++)
                LDSM_X4(af[mt], sa + aoff + mt * 16 * STRIDE + ks * 32);
            #pragma unroll
            for (int nt = 0; nt < 4; nt++)
                LDSM_X2(bf[nt], sb + boff + nt * 8 * STRIDE + ks * 32);
            #pragma unroll
            for (int mt = 0; mt < 4; mt++)
                #pragma unroll
                for (int nt = 0; nt < 4; nt++)
                    MMA16816(acc[mt][nt], af[mt], bf[nt]);
        }
    };

    #pragma unroll
    for (int s = 0; s < 3; s++) {
        load_stage(s, s);
        CP_COMMIT();
    }

    for (int kt = 0; kt < nk; kt++) {
        CP_WAIT2();
        __syncthreads();
        load_stage(kt + 3, (kt + 3) & 3);
        CP_COMMIT();
        compute(kt & 3);
    }

    #pragma unroll
    for (int mt = 0; mt < 4; mt++) {
        const int r0 = m0 + wm + mt * 16 + grp;
        #pragma unroll
        for (int half = 0; half < 2; half++) {
            const int gm = r0 + half * 8;
            if (gm >= M) continue;
            #pragma unroll
            for (int nt = 0; nt < 4; nt++) {
                const int gn = n0 + wn + nt * 8 + idx * 2;
                if (gn >= N) continue;
                float v0 = acc[mt][nt][half * 2 + 0];
                float v1 = acc[mt][nt][half * 2 + 1];
                if (HAS_BIAS) { v0 += bias[gn]; v1 += bias[gn + 1]; }
                float* p = C + (size_t)gm * ldc + gn;
                if (ACCUM) {
                    float2 old = *reinterpret_cast<float2*>(p);
                    v0 += old.x; v1 += old.y;
                }
                *reinterpret_cast<float2*>(p) = make_float2(v0, v1);
            }
        }
    }
}

// =====================================================================
// FUSED ATTENTION (unchanged)
// =====================================================================
#define KSTR 144
#define PSTR 464
#define SM_Q 0
#define SM_K (SM_Q + 128 * KSTR)
#define SM_V (SM_K + SKP_ * KSTR)
#define SM_P (SM_V + SKP_ * KSTR)
#define ATT_SMEM (SM_P + 128 * PSTR)     // 142336

__global__ __launch_bounds__(256)
void attn_fused(const __half* __restrict__ qh, const __half* __restrict__ kh,
                const __half* __restrict__ vh, __half* __restrict__ o)
{
    extern __shared__ __align__(128) uint8_t sm[];
    __shared__ float red[128][4];

    const int z  = blockIdx.y;
    const int b  = z / H_, h = z % H_;
    const int m0 = blockIdx.x * 128;

    const int t    = threadIdx.x;
    const int warp = t >> 5, lane = t & 31;
    const int wm   = (warp >> 2) * 64;
    const int wn   = (warp & 3) * 56;
    const int wnv  = (warp & 3) * 16;
    const int grp  = lane >> 2;
    const int idx  = lane & 3;
    const int wc   = warp & 3;

    const uint32_t sq = smem_u32(sm) + SM_Q;
    const uint32_t sk = smem_u32(sm) + SM_K;
    const uint32_t sv = smem_u32(sm) + SM_V;
    const uint32_t sp = smem_u32(sm) + SM_P;

    const __half* qbase = qh + ((size_t)b * S_) * W_ + h * HD_;
    const __half* kbase = kh + ((size_t)b * S_) * W_ + h * HD_;
    const __half* vbase = vh + ((size_t)b * S_) * W_ + h * HD_;

    #pragma unroll
    for (int i = 0; i < 4; i++) {
        const int c = t + i * 256;
        const int r = c >> 3, ck = c & 7;
        cp16(sq + r * KSTR + ck * 16, qbase + (size_t)(m0 + r) * W_ + ck * 8,
             (m0 + r) < S_);
    }
    #pragma unroll
    for (int i = 0; i < 7; i++) {
        const int c = t + i * 256;
        const int r = c >> 3, ck = c & 7;
        cp16(sk + r * KSTR + ck * 16, kbase + (size_t)r * W_ + ck * 8, r < S_);
        cp16(sv + r * KSTR + ck * 16, vbase + (size_t)r * W_ + ck * 8, r < S_);
    }
    CP_COMMIT();
    CP_WAIT0();
    __syncthreads();

    float acc[4][7][4];
    #pragma unroll
    for (int a = 0; a < 4; a++)
        #pragma unroll
        for (int n = 0; n < 7; n++)
            #pragma unroll
            for (int c = 0; c < 4; c++) acc[a][n][c] = 0.0f;

    const int aoffq = (wm + (lane & 15)) * KSTR + (lane >> 4) * 16;
    const int boffk = ((lane & 7)) * KSTR + ((lane >> 3) & 1) * 16;

    #pragma unroll
    for (int ks = 0; ks < 4; ks++) {
        uint32_t af[4][4], bf[7][2];
        #pragma unroll
        for (int mt = 0; mt < 4; mt++)
            LDSM_X4(af[mt], sq + aoffq + mt * 16 * KSTR + ks * 32);
        #pragma unroll
        for (int nt = 0; nt < 7; nt++)
            LDSM_X2(bf[nt], sk + boffk + (wn + nt * 8) * KSTR + ks * 32);
        #pragma unroll
        for (int mt = 0; mt < 4; mt++)
            #pragma unroll
            for (int nt = 0; nt < 7; nt++)
                MMA16816(acc[mt][nt], af[mt], bf[nt]);
    }

    #pragma unroll
    for (int mt = 0; mt < 4; mt++)
        #pragma unroll
        for (int nt = 0; nt < 7; nt++)
            #pragma unroll
            for (int c = 0; c < 4; c++) {
                const int col = wn + nt * 8 + idx * 2 + (c & 1);
                acc[mt][nt][c] = (col < S_) ? acc[mt][nt][c] * 0.125f : -1e30f;
            }

    float gmax[4][2], gsum[4][2];

    #pragma unroll
    for (int mt = 0; mt < 4; mt++)
        #pragma unroll
        for (int hf = 0; hf < 2; hf++) {
            float m = -1e30f;
            #pragma unroll
            for (int nt = 0; nt < 7; nt++) {
                m = fmaxf(m, acc[mt][nt][hf * 2 + 0]);
                m = fmaxf(m, acc[mt][nt][hf * 2 + 1]);
            }
            m = fmaxf(m, __shfl_xor_sync(0xffffffffu, m, 1));
            m = fmaxf(m, __shfl_xor_sync(0xffffffffu, m, 2));
            if (idx == 0) red[wm + mt * 16 + hf * 8 + grp][wc] = m;
        }
    __syncthreads();
    #pragma unroll
    for (int mt = 0; mt < 4; mt++)
        #pragma unroll
        for (int hf = 0; hf < 2; hf++) {
            const int row = wm + mt * 16 + hf * 8 + grp;
            gmax[mt][hf] = fmaxf(fmaxf(red[row][0], red[row][1]),
                                 fmaxf(red[row][2], red[row][3]));
        }
    __syncthreads();

    #pragma unroll
    for (int mt = 0; mt < 4; mt++)
        #pragma unroll
        for (int hf = 0; hf < 2; hf++) {
            float s = 0.f;
            #pragma unroll
            for (int nt = 0; nt < 7; nt++) {
                float e0 = expf(acc[mt][nt][hf * 2 + 0] - gmax[mt][hf]);
                float e1 = expf(acc[mt][nt][hf * 2 + 1] - gmax[mt][hf]);
                acc[mt][nt][hf * 2 + 0] = e0;
                acc[mt][nt][hf * 2 + 1] = e1;
                s += e0 + e1;
            }
            s += __shfl_xor_sync(0xffffffffu, s, 1);
            s += __shfl_xor_sync(0xffffffffu, s, 2);
            if (idx == 0) red[wm + mt * 16 + hf * 8 + grp][wc] = s;
        }
    __syncthreads();
    #pragma unroll
    for (int mt = 0; mt < 4; mt++)
        #pragma unroll
        for (int hf = 0; hf < 2; hf++) {
            const int row = wm + mt * 16 + hf * 8 + grp;
            gsum[mt][hf] = red[row][0] + red[row][1] + red[row][2] + red[row][3];
        }

    #pragma unroll
    for (int mt = 0; mt < 4; mt++)
        #pragma unroll
        for (int hf = 0; hf < 2; hf++) {
            const int row = wm + mt * 16 + hf * 8 + grp;
            const float inv = 1.0f / gsum[mt][hf];
            #pragma unroll
            for (int nt = 0; nt < 7; nt++) {
                const int col = wn + nt * 8 + idx * 2;
                *reinterpret_cast<__half2*>(reinterpret_cast<uint8_t*>(sm) + SM_P +
                                            row * PSTR + col * 2) =
                    __floats2half2_rn(acc[mt][nt][hf * 2 + 0] * inv,
                                      acc[mt][nt][hf * 2 + 1] * inv);
            }
        }
    __syncthreads();

    float acc2[4][2][4];
    #pragma unroll
    for (int a = 0; a < 4; a++)
        #pragma unroll
        for (int n = 0; n < 2; n++)
            #pragma unroll
            for (int c = 0; c < 4; c++) acc2[a][n][c] = 0.0f;

    const int aoffp = (wm + (lane & 15)) * PSTR + (lane >> 4) * 16;

    #pragma unroll
    for (int ks = 0; ks < 14; ks++) {
        uint32_t af[4][4], bf[2][2];
        #pragma unroll
        for (int mt = 0; mt < 4; mt++)
            LDSM_X4(af[mt], sp + aoffp + mt * 16 * PSTR + ks * 32);
        #pragma unroll
        for (int nt = 0; nt < 2; nt++)
            LDSM_X2T(bf[nt], sv + (ks * 16 + (lane & 7) + ((lane >> 3) & 1) * 8) * KSTR
                              + (wnv + nt * 8) * 2);
        #pragma unroll
        for (int mt = 0; mt < 4; mt++)
            #pragma unroll
            for (int nt = 0; nt < 2; nt++)
                MMA16816(acc2[mt][nt], af[mt], bf[nt]);
    }

    __half* obase = o + ((size_t)b * S_) * W_ + h * HD_;
    #pragma unroll
    for (int mt = 0; mt < 4; mt++)
        #pragma unroll
        for (int hf = 0; hf < 2; hf++) {
            const int gs = m0 + wm + mt * 16 + hf * 8 + grp;
            if (gs >= S_) continue;
            #pragma unroll
            for (int nt = 0; nt < 2; nt++) {
                const int d = wnv + nt * 8 + idx * 2;
                *reinterpret_cast<__half2*>(obase + (size_t)gs * W_ + d) =
                    __floats2half2_rn(acc2[mt][nt][hf * 2 + 0],
                                      acc2[mt][nt][hf * 2 + 1]);
            }
        }
}

// ---------------- transpose f32->f16 ----------------
__global__ void transpose_h_kernel(const float* __restrict__ in, __half* __restrict__ out,
                                   int R, int Cc, long long ldOut, int rowOff)
{
    __shared__ float tile[32][33];
    const size_t li = (size_t)blockIdx.z * R * Cc;
    const int c0 = blockIdx.x * 32, r0 = blockIdx.y * 32;
    const int x = threadIdx.x, y = threadIdx.y;
    #pragma unroll
    for (int j = 0; j < 32; j += 8)
        tile[y + j][x] = in[li + (size_t)(r0 + y + j) * Cc + c0 + x];
    __syncthreads();
    #pragma unroll
    for (int j = 0; j < 32; j += 8)
        out[(size_t)blockIdx.z * ldOut + (size_t)(rowOff + c0 + y + j) * R + r0 + x] =
            __float2half(tile[x][y + j]);
}

__global__ void convw_h_kernel(const float* __restrict__ in, __half* __restrict__ out)
{
    int i = blockIdx.x * 256 + threadIdx.x;
    if (i < W_ * W_) out[i] = __float2half(in[i]);
}

__global__ void bias_concat_kernel(const float* __restrict__ bq, const float* __restrict__ bk,
                                   const float* __restrict__ bv, float* __restrict__ o)
{
    int i = blockIdx.x * 256 + threadIdx.x;
    if (i >= L_ * QKV_) return;
    const int l = i / QKV_, j = i % QKV_;
    float v = (j < W_) ? bq[l * W_ + j]
            : (j < 2 * W_) ? bk[l * W_ + j - W_]
            : bv[l * W_ + j - 2 * W_];
    o[i] = v;
}

// ---------------- im2col ----------------
__global__ void im2col_kernel(const float* __restrict__ x, __half* __restrict__ out)
{
    const int total = B_ * NPATCH_ * W_;
    int idx = blockIdx.x * 256 + threadIdx.x;
    if (idx >= total) return;
    const int kk = idx % W_;
    const int r  = idx / W_;
    const int b  = r / NPATCH_;
    const int p  = r % NPATCH_;
    const int ph = p / 14, pw = p % 14;
    const int c  = kk >> 8;
    const int py = (kk >> 4) & 15;
    const int px = kk & 15;
    out[idx] = __float2half(
        x[(((size_t)b * C_ + c) * IMG_ + ph * P_ + py) * IMG_ + pw * P_ + px]);
}

// ---------------- assemble ----------------
__global__ void assemble_kernel(const float* __restrict__ tok,
                                const float* __restrict__ cls,
                                const float* __restrict__ pe,
                                float* __restrict__ h)
{
    int idx = blockIdx.x * 256 + threadIdx.x;
    if (idx >= BSW_) return;
    const int w  = idx % W_;
    const int bs = idx / W_;
    const int s  = bs % S_;
    const int b  = bs / S_;
    float v = (s == 0) ? cls[w] : tok[((size_t)b * NPATCH_ + (s - 1)) * W_ + w];
    h[idx] = v + pe[(size_t)s * W_ + w];
}

// ---------------- layernorm: warp-per-row ----------------
__global__ void layernorm_kernel(const float* __restrict__ x,
                                 const float* __restrict__ gamma,
                                 const float* __restrict__ beta,
                                 __half* __restrict__ y, int nrows)
{
    const int warp = threadIdx.x >> 5, lane = threadIdx.x & 31;
    const int row = blockIdx.x * 8 + warp;
    if (row >= nrows) return;

    const float4* xr = reinterpret_cast<const float4*>(x + (size_t)row * W_);
    float4 v[6];
    float s = 0.f, s2 = 0.f;
    #pragma unroll
    for (int i = 0; i < 6; i++) {
        v[i] = xr[lane + 32 * i];
        s  += v[i].x + v[i].y + v[i].z + v[i].w;
        s2 += v[i].x * v[i].x + v[i].y * v[i].y + v[i].z * v[i].z + v[i].w * v[i].w;
    }
    #pragma unroll
    for (int off = 16; off > 0; off >>= 1) {
        s  += __shfl_xor_sync(0xffffffffu, s, off);
        s2 += __shfl_xor_sync(0xffffffffu, s2, off);
    }
    const float mean = s * (1.0f / W_);
    const float inv  = rsqrtf(s2 * (1.0f / W_) - mean * mean + 1e-5f);

    const float4* gp = reinterpret_cast<const float4*>(gamma);
    const float4* bp = reinterpret_cast<const float4*>(beta);
    uint2* yr = reinterpret_cast<uint2*>(y + (size_t)row * W_);
    #pragma unroll
    for (int i = 0; i < 6; i++) {
        const int c4 = lane + 32 * i;
        float4 g = gp[c4], bb = bp[c4];
        float o0 = (v[i].x - mean) * inv * g.x + bb.x;
        float o1 = (v[i].y - mean) * inv * g.y + bb.y;
        float o2 = (v[i].z - mean) * inv * g.z + bb.z;
        float o3 = (v[i].w - mean) * inv * g.w + bb.w;
        __half2 h0 = __floats2half2_rn(o0, o1);
        __half2 h1 = __floats2half2_rn(o2, o3);
        yr[c4] = make_uint2(*reinterpret_cast<uint32_t*>(&h0),
                            *reinterpret_cast<uint32_t*>(&h1));
    }
}

// ---------------- gather / l2norm ----------------
__global__ void gather_cls_kernel(const float* __restrict__ h, __half* __restrict__ cls)
{
    int idx = blockIdx.x * 256 + threadIdx.x;
    if (idx >= B_ * W_) return;
    const int b = idx / W_, w = idx % W_;
    cls[idx] = __float2half(h[(size_t)b * S_ * W_ + w]);
}

__global__ void l2norm_kernel(float* __restrict__ out)
{
    const int row = blockIdx.x;
    float* r = out + (size_t)row * E_;
    float s = 0.f;
    for (int i = threadIdx.x; i < E_; i += 256) { float v = r[i]; s += v * v; }
    for (int off = 16; off > 0; off >>= 1) s += __shfl_down_sync(0xffffffffu, s, off);
    __shared__ float rs[8];
    const int warp = threadIdx.x >> 5, lane = threadIdx.x & 31;
    if (lane == 0) rs[warp] = s;
    __syncthreads();
    __shared__ float inv_sh;
    if (threadIdx.x == 0) {
        float ts = 0.f;
        for (int i = 0; i < 8; i++) ts += rs[i];
        inv_sh = rsqrtf(ts);
    }
    __syncthreads();
    const float inv = inv_sh;
    for (int i = threadIdx.x; i < E_; i += 256) r[i] *= inv;
}

// ---------------- launch ----------------
extern "C" void kernel_launch(void* const* d_in, const int* in_sizes, int n_in,
                              void* d_out, int out_size)
{
    (void)in_sizes; (void)n_in; (void)out_size;

    const float* x       = (const float*)d_in[0];
    const float* conv_w  = (const float*)d_in[1];
    const float* conv_b  = (const float*)d_in[2];
    const float* cls_tok = (const float*)d_in[3];
    const float* pe      = (const float*)d_in[4];
    const float* ln1_g   = (const float*)d_in[5];
    const float* ln1_b   = (const float*)d_in[6];
    const float* wq      = (const float*)d_in[7];
    const float* bq      = (const float*)d_in[8];
    const float* wk      = (const float*)d_in[9];
    const float* bk      = (const float*)d_in[10];
    const float* wv      = (const float*)d_in[11];
    const float* bv      = (const float*)d_in[12];
    const float* wo      = (const float*)d_in[13];
    const float* bo      = (const float*)d_in[14];
    const float* ln2_g   = (const float*)d_in[15];
    const float* ln2_b   = (const float*)d_in[16];
    const float* w1      = (const float*)d_in[17];
    const float* b1      = (const float*)d_in[18];
    const float* w2      = (const float*)d_in[19];
    const float* b2      = (const float*)d_in[20];
    const float* proj    = (const float*)d_in[21];
    float* out           = (float*)d_out;

    float  *h, *tok, *bqkv;
    __half *y, *qh, *kh, *vh, *o, *ff, *i2c, *cls, *convw16;
    __half *wqkvT, *woT, *w1T, *w2T, *projT;
    cudaGetSymbolAddress((void**)&h,    g_h);
    cudaGetSymbolAddress((void**)&y,    g_y);
    cudaGetSymbolAddress((void**)&qh,   g_qh);
    cudaGetSymbolAddress((void**)&kh,   g_kh);
    cudaGetSymbolAddress((void**)&vh,   g_vh);
    cudaGetSymbolAddress((void**)&o,    g_o);
    cudaGetSymbolAddress((void**)&ff,   g_ff);
    cudaGetSymbolAddress((void**)&i2c,  g_im2col);
    cudaGetSymbolAddress((void**)&tok,  g_tok);
    cudaGetSymbolAddress((void**)&cls,  g_cls);
    cudaGetSymbolAddress((void**)&convw16, g_convw16);
    cudaGetSymbolAddress((void**)&wqkvT, g_wqkvT);
    cudaGetSymbolAddress((void**)&bqkv,  g_bqkv);
    cudaGetSymbolAddress((void**)&woT,  g_woT);
    cudaGetSymbolAddress((void**)&w1T,  g_w1T);
    cudaGetSymbolAddress((void**)&w2T,  g_w2T);
    cudaGetSymbolAddress((void**)&projT, g_projT);

    cudaFuncSetAttribute(gemm_wide<1,0,0,0>, cudaFuncAttributeMaxDynamicSharedMemorySize, WSMEM);
    cudaFuncSetAttribute(gemm_wide<1,0,0,3>, cudaFuncAttributeMaxDynamicSharedMemorySize, WSMEM);
    cudaFuncSetAttribute(gemm_wide<0,0,0,0>, cudaFuncAttributeMaxDynamicSharedMemorySize, WSMEM);
    cudaFuncSetAttribute(gemm_wide<1,0,1,1>, cudaFuncAttributeMaxDynamicSharedMemorySize, WSMEM);
    cudaFuncSetAttribute(gemm_n<1,1>, cudaFuncAttributeMaxDynamicSharedMemorySize, NSMEM);
    cudaFuncSetAttribute(attn_fused, cudaFuncAttributeMaxDynamicSharedMemorySize, ATT_SMEM);

    const int M  = B_ * S_;       // 6304
    const int Mp = B_ * NPATCH_;  // 6272
    dim3 blkT(32, 8);

    im2col_kernel<<<(Mp * W_ + 255) / 256, 256>>>(x, i2c);
    convw_h_kernel<<<(W_ * W_ + 255) / 256, 256>>>(conv_w, convw16);
    transpose_h_kernel<<<dim3(W_/32, W_/32, L_), blkT>>>(wq, wqkvT, W_, W_, (long long)QKV_*W_, 0);
    transpose_h_kernel<<<dim3(W_/32, W_/32, L_), blkT>>>(wk, wqkvT, W_, W_, (long long)QKV_*W_, W_);
    transpose_h_kernel<<<dim3(W_/32, W_/32, L_), blkT>>>(wv, wqkvT, W_, W_, (long long)QKV_*W_, 2*W_);
    bias_concat_kernel<<<(L_*QKV_ + 255) / 256, 256>>>(bq, bk, bv, bqkv);
    transpose_h_kernel<<<dim3(W_/32,  W_/32,  L_), blkT>>>(wo, woT, W_, W_, (long long)W_*W_, 0);
    transpose_h_kernel<<<dim3(FF_/32, W_/32,  L_), blkT>>>(w1, w1T, W_, FF_, (long long)W_*FF_, 0);
    transpose_h_kernel<<<dim3(W_/32,  FF_/32, L_), blkT>>>(w2, w2T, FF_, W_, (long long)FF_*W_, 0);
    transpose_h_kernel<<<dim3(E_/32,  W_/32,  1),  blkT>>>(proj, projT, W_, E_, (long long)W_*E_, 0);

    {   // patch embed GEMM -> tok (f32)
        dim3 grid(3, (Mp + 127) / 128, 1);
        gemm_wide<1,0,0,0><<<grid, 512, WSMEM>>>(i2c, convw16, conv_b, tok,
            nullptr, nullptr, nullptr, Mp, W_, W_, W_, W_, W_);
    }
    assemble_kernel<<<(BSW_ + 255) / 256, 256>>>(tok, cls_tok, pe, h);

    dim3 gridQKV(QKV_ / 256, (M + 127) / 128, 1);
    dim3 gridN  (W_ / 128, (M + 127) / 128, 1);
    dim3 gridFF (FF_ / 256, (M + 127) / 128, 1);
    dim3 gridAtt(2, B_ * H_, 1);
    const int lnGrid = (M + 7) / 8;

    for (int l = 0; l < L_; l++) {
        const size_t bOff = (size_t)l * W_;

        layernorm_kernel<<<lnGrid, 256>>>(h, ln1_g + bOff, ln1_b + bOff, y, M);
        gemm_wide<1,0,0,3><<<gridQKV, 512, WSMEM>>>(y, wqkvT + (size_t)l * QKV_ * W_,
            bqkv + (size_t)l * QKV_, nullptr, qh, kh, vh,
            M, QKV_, W_, W_, W_, 0);
        attn_fused<<<gridAtt, 256, ATT_SMEM>>>(qh, kh, vh, o);
        gemm_n<1,1><<<gridN, 256, NSMEM>>>(o, woT + (size_t)l * W_ * W_,
            bo + bOff, h, M, W_, W_, W_, W_, W_);
        layernorm_kernel<<<lnGrid, 256>>>(h, ln2_g + bOff, ln2_b + bOff, y, M);
        gemm_wide<1,0,1,1><<<gridFF, 512, WSMEM>>>(y, w1T + (size_t)l * W_ * FF_,
            b1 + (size_t)l * FF_, nullptr, ff, nullptr, nullptr,
            M, FF_, W_, W_, W_, FF_);
        gemm_n<1,1><<<gridN, 256, NSMEM>>>(ff, w2T + (size_t)l * FF_ * W_,
            b2 + bOff, h, M, W_, FF_, FF_, FF_, W_);
    }

    gather_cls_kernel<<<(B_ * W_ + 255) / 256, 256>>>(h, cls);
    {
        dim3 grid(2, 1, 1);
        gemm_wide<0,0,0,0><<<grid, 512, WSMEM>>>(cls, projT, nullptr, out,
            nullptr, nullptr, nullptr, B_, E_, W_, W_, W_, E_);
    }
    l2norm_kernel<<<B_, 256>>>(out);
}

// round 14
// speedup vs baseline: 1.0858x; 1.0858x over previous
#include <cuda_runtime.h>
#include <cuda_fp16.h>
#include <math.h>
#include <stdint.h>

// ---------------- problem constants ----------------
#define B_  32
#define C_  3
#define IMG_ 224
#define P_  16
#define W_  768
#define L_  12
#define H_  12
#define S_  197
#define HD_ 64
#define FF_ 3072
#define E_  512
#define NPATCH_ 196
#define BSW_ (B_*S_*W_)
#define SKP_ 224
#define QKV_ 2304

// ---------------- scratch ----------------
__device__ float  g_h   [BSW_];
__device__ __half g_y   [BSW_];
__device__ __half g_qh  [BSW_];
__device__ __half g_kh  [BSW_];
__device__ __half g_vh  [BSW_];
__device__ __half g_o   [BSW_];
__device__ __half g_ff  [B_*S_*FF_];
__device__ __half g_im2col[B_*NPATCH_*W_];
__device__ float  g_tok [B_*NPATCH_*W_];
__device__ __half g_cls [B_*W_];
__device__ __half g_convw16[W_*W_];
__device__ __half g_wqkvT[L_*QKV_*W_];
__device__ float  g_bqkv [L_*QKV_];
__device__ __half g_woT [L_*W_*W_];
__device__ __half g_w1T [L_*W_*FF_];
__device__ __half g_w2T [L_*FF_*W_];
__device__ __half g_projT[W_*E_];

__device__ __forceinline__ float gelu_exact(float v) {
    return 0.5f * v * (1.0f + erff(v * 0.70710678118654752f));
}
__device__ __forceinline__ uint32_t smem_u32(const void* p) {
    uint32_t a;
    asm("{ .reg .u64 t; cvta.to.shared.u64 t, %1; cvt.u32.u64 %0, t; }" : "=r"(a) : "l"(p));
    return a;
}

#define LDSM_X4(r, addr) \
    asm volatile("ldmatrix.sync.aligned.m8n8.x4.shared.b16 {%0,%1,%2,%3}, [%4];" \
        : "=r"((r)[0]), "=r"((r)[1]), "=r"((r)[2]), "=r"((r)[3]) : "r"(addr))
#define LDSM_X2(r, addr) \
    asm volatile("ldmatrix.sync.aligned.m8n8.x2.shared.b16 {%0,%1}, [%2];" \
        : "=r"((r)[0]), "=r"((r)[1]) : "r"(addr))
#define LDSM_X2T(r, addr) \
    asm volatile("ldmatrix.sync.aligned.m8n8.x2.trans.shared.b16 {%0,%1}, [%2];" \
        : "=r"((r)[0]), "=r"((r)[1]) : "r"(addr))

__device__ __forceinline__ void cp16(uint32_t dst, const void* src, bool valid) {
    int sz = valid ? 16 : 0;
    asm volatile("cp.async.cg.shared.global [%0], [%1], 16, %2;"
                 :: "r"(dst), "l"(src), "r"(sz));
}
#define CP_COMMIT() asm volatile("cp.async.commit_group;" ::: "memory")
#define CP_WAIT2()  asm volatile("cp.async.wait_group 2;" ::: "memory")
#define CP_WAIT0()  asm volatile("cp.async.wait_group 0;" ::: "memory")

#define MMA16816(acc, af, bf) \
    asm volatile("mma.sync.aligned.m16n8k16.row.col.f32.f16.f16.f32 " \
        "{%0,%1,%2,%3}, {%4,%5,%6,%7}, {%8,%9}, {%0,%1,%2,%3};" \
        : "+f"((acc)[0]), "+f"((acc)[1]), "+f"((acc)[2]), "+f"((acc)[3]) \
        : "r"((af)[0]), "r"((af)[1]), "r"((af)[2]), "r"((af)[3]), \
          "r"((bf)[0]), "r"((bf)[1]))

// =====================================================================
// WIDE GEMM (round-10 champion): 128x256 CTA tile, 512 threads
// (16 warps x 64x32), KT=32, 4-stage cp.async.
// OUT_MODE: 0 = f32 C (opt ACCUM/bias), 1 = f16 Ch (opt gelu), 3 = QKV route.
// =====================================================================
#define WSTRIDE 80
#define ASTG (128 * WSTRIDE)
#define BSTG (256 * WSTRIDE)
#define WSMEM (4 * (ASTG + BSTG))         // 122880

template<int HAS_BIAS, int ACCUM, int DO_GELU, int OUT_MODE>
__global__ __launch_bounds__(512)
void gemm_wide(const __half* __restrict__ A, const __half* __restrict__ Bt,
               const float* __restrict__ bias, float* __restrict__ C,
               __half* __restrict__ Ch, __half* __restrict__ Kh,
               __half* __restrict__ Vh,
               int M, int N, int K, int lda, int ldb, int ldc)
{
    extern __shared__ __align__(128) uint8_t sm[];
    uint8_t* smA = sm;
    uint8_t* smB = sm + 4 * ASTG;

    const int t    = threadIdx.x;
    const int warp = t >> 5, lane = t & 31;
    const int m0   = blockIdx.y * 128;
    const int n0   = blockIdx.x * 256;
    const int wm   = (warp >> 3) * 64;
    const int wn   = (warp & 7) * 32;
    const int grp  = lane >> 2;
    const int idx  = lane & 3;

    float acc[4][4][4];
    #pragma unroll
    for (int a = 0; a < 4; a++)
        #pragma unroll
        for (int b = 0; b < 4; b++)
            #pragma unroll
            for (int c = 0; c < 4; c++) acc[a][b][c] = 0.0f;

    const uint32_t saA = smem_u32(smA);
    const uint32_t saB = smem_u32(smB);

    const int rowX = t >> 2;
    const int ck   = t & 3;
    const bool aValid  = (m0 + rowX) < M;
    const bool bValid0 = (n0 + rowX) < N;
    const bool bValid1 = (n0 + rowX + 128) < N;
    const __half* aBase  = A  + (size_t)(m0 + rowX) * lda + ck * 8;
    const __half* bBase0 = Bt + (size_t)(n0 + rowX) * ldb + ck * 8;
    const __half* bBase1 = Bt + (size_t)(n0 + rowX + 128) * ldb + ck * 8;
    const uint32_t dA  = saA + rowX * WSTRIDE + ck * 16;
    const uint32_t dB0 = saB + rowX * WSTRIDE + ck * 16;
    const uint32_t dB1 = saB + (rowX + 128) * WSTRIDE + ck * 16;

    const int nk = K / 32;

    auto load_stage = [&](int kt, int buf) {
        const bool ok = kt < nk;
        const int ko = ok ? kt * 32 : 0;
        cp16(dA  + buf * ASTG, aBase  + ko, ok && aValid);
        cp16(dB0 + buf * BSTG, bBase0 + ko, ok && bValid0);
        cp16(dB1 + buf * BSTG, bBase1 + ko, ok && bValid1);
    };

    const int aoff = (wm + (lane & 15)) * WSTRIDE + (lane >> 4) * 16;
    const int boff = (wn + (lane & 7))  * WSTRIDE + ((lane >> 3) & 1) * 16;

    auto compute = [&](int buf) {
        const uint32_t sa = saA + buf * ASTG;
        const uint32_t sb = saB + buf * BSTG;
        #pragma unroll
        for (int ks = 0; ks < 2; ks++) {
            uint32_t af[4][4], bf[4][2];
            #pragma unroll
            for (int mt = 0; mt < 4; mt++)
                LDSM_X4(af[mt], sa + aoff + mt * 16 * WSTRIDE + ks * 32);
            #pragma unroll
            for (int nt = 0; nt < 4; nt++)
                LDSM_X2(bf[nt], sb + boff + nt * 8 * WSTRIDE + ks * 32);
            #pragma unroll
            for (int mt = 0; mt < 4; mt++)
                #pragma unroll
                for (int nt = 0; nt < 4; nt++)
                    MMA16816(acc[mt][nt], af[mt], bf[nt]);
        }
    };

    #pragma unroll
    for (int s = 0; s < 3; s++) {
        load_stage(s, s);
        CP_COMMIT();
    }

    for (int kt = 0; kt < nk; kt++) {
        CP_WAIT2();
        __syncthreads();
        load_stage(kt + 3, (kt + 3) & 3);
        CP_COMMIT();
        compute(kt & 3);
    }

    #pragma unroll
    for (int mt = 0; mt < 4; mt++) {
        const int r0 = m0 + wm + mt * 16 + grp;
        #pragma unroll
        for (int half = 0; half < 2; half++) {
            const int gm = r0 + half * 8;
            if (gm >= M) continue;
            #pragma unroll
            for (int nt = 0; nt < 4; nt++) {
                const int gn = n0 + wn + nt * 8 + idx * 2;
                if (gn >= N) continue;
                float v0 = acc[mt][nt][half * 2 + 0];
                float v1 = acc[mt][nt][half * 2 + 1];
                if (HAS_BIAS) { v0 += bias[gn]; v1 += bias[gn + 1]; }
                if (DO_GELU)  { v0 = gelu_exact(v0); v1 = gelu_exact(v1); }
                if (OUT_MODE == 3) {
                    __half2 hv = __floats2half2_rn(v0, v1);
                    if (gn < W_)
                        *reinterpret_cast<__half2*>(Ch + (size_t)gm * W_ + gn) = hv;
                    else if (gn < 2 * W_)
                        *reinterpret_cast<__half2*>(Kh + (size_t)gm * W_ + gn - W_) = hv;
                    else
                        *reinterpret_cast<__half2*>(Vh + (size_t)gm * W_ + gn - 2 * W_) = hv;
                } else if (OUT_MODE == 1) {
                    *reinterpret_cast<__half2*>(Ch + (size_t)gm * ldc + gn) =
                        __floats2half2_rn(v0, v1);
                } else {
                    float* p = C + (size_t)gm * ldc + gn;
                    if (ACCUM) {
                        float2 old = *reinterpret_cast<float2*>(p);
                        v0 += old.x; v1 += old.y;
                    }
                    *reinterpret_cast<float2*>(p) = make_float2(v0, v1);
                }
            }
        }
    }
}

// =====================================================================
// NARROW GEMM: 128x128 tile, 256 threads, 2 CTAs/SM (N=768 GEMMs).
// =====================================================================
#define STRIDE 80
#define STAGEB (128 * STRIDE)
#define NSMEM (8 * STAGEB)   // 81920

template<int HAS_BIAS, int ACCUM>
__global__ __launch_bounds__(256, 2)
void gemm_n(const __half* __restrict__ A, const __half* __restrict__ Bt,
            const float* __restrict__ bias, float* __restrict__ C,
            int M, int N, int K, int lda, int ldb, int ldc)
{
    extern __shared__ __align__(128) uint8_t sm[];
    uint8_t* smA = sm;
    uint8_t* smB = sm + 4 * STAGEB;

    const int t    = threadIdx.x;
    const int warp = t >> 5, lane = t & 31;
    const int m0   = blockIdx.y * 128;
    const int n0   = blockIdx.x * 128;
    const int wm   = (warp >> 2) * 64;
    const int wn   = (warp & 3) * 32;
    const int grp  = lane >> 2;
    const int idx  = lane & 3;

    float acc[4][4][4];
    #pragma unroll
    for (int a = 0; a < 4; a++)
        #pragma unroll
        for (int b = 0; b < 4; b++)
            #pragma unroll
            for (int c = 0; c < 4; c++) acc[a][b][c] = 0.0f;

    const uint32_t saA = smem_u32(smA);
    const uint32_t saB = smem_u32(smB);

    const int rowL = t >> 1;
    const int ck0  = (t & 1) * 2;
    const bool aValid = (m0 + rowL) < M;
    const bool bValid = (n0 + rowL) < N;
    const __half* aBase = A + (size_t)(m0 + rowL) * lda + ck0 * 8;
    const __half* bBase = Bt + (size_t)(n0 + rowL) * ldb + ck0 * 8;
    const uint32_t dA = saA + rowL * STRIDE + ck0 * 16;
    const uint32_t dB = saB + rowL * STRIDE + ck0 * 16;

    const int nk = K / 32;

    auto load_stage = [&](int kt, int buf) {
        const bool ok = kt < nk;
        const int ko = ok ? kt * 32 : 0;
        cp16(dA + buf * STAGEB,      aBase + ko,     ok && aValid);
        cp16(dA + buf * STAGEB + 16, aBase + ko + 8, ok && aValid);
        cp16(dB + buf * STAGEB,      bBase + ko,     ok && bValid);
        cp16(dB + buf * STAGEB + 16, bBase + ko + 8, ok && bValid);
    };

    const int aoff = (wm + (lane & 15)) * STRIDE + (lane >> 4) * 16;
    const int boff = (wn + (lane & 7))  * STRIDE + ((lane >> 3) & 1) * 16;

    auto compute = [&](int buf) {
        const uint32_t sa = saA + buf * STAGEB;
        const uint32_t sb = saB + buf * STAGEB;
        #pragma unroll
        for (int ks = 0; ks < 2; ks++) {
            uint32_t af[4][4], bf[4][2];
            #pragma unroll
            for (int mt = 0; mt < 4; mt++)
                LDSM_X4(af[mt], sa + aoff + mt * 16 * STRIDE + ks * 32);
            #pragma unroll
            for (int nt = 0; nt < 4; nt++)
                LDSM_X2(bf[nt], sb + boff + nt * 8 * STRIDE + ks * 32);
            #pragma unroll
            for (int mt = 0; mt < 4; mt++)
                #pragma unroll
                for (int nt = 0; nt < 4; nt++)
                    MMA16816(acc[mt][nt], af[mt], bf[nt]);
        }
    };

    #pragma unroll
    for (int s = 0; s < 3; s++) {
        load_stage(s, s);
        CP_COMMIT();
    }

    for (int kt = 0; kt < nk; kt++) {
        CP_WAIT2();
        __syncthreads();
        load_stage(kt + 3, (kt + 3) & 3);
        CP_COMMIT();
        compute(kt & 3);
    }

    #pragma unroll
    for (int mt = 0; mt < 4; mt++) {
        const int r0 = m0 + wm + mt * 16 + grp;
        #pragma unroll
        for (int half = 0; half < 2; half++) {
            const int gm = r0 + half * 8;
            if (gm >= M) continue;
            #pragma unroll
            for (int nt = 0; nt < 4; nt++) {
                const int gn = n0 + wn + nt * 8 + idx * 2;
                if (gn >= N) continue;
                float v0 = acc[mt][nt][half * 2 + 0];
                float v1 = acc[mt][nt][half * 2 + 1];
                if (HAS_BIAS) { v0 += bias[gn]; v1 += bias[gn + 1]; }
                float* p = C + (size_t)gm * ldc + gn;
                if (ACCUM) {
                    float2 old = *reinterpret_cast<float2*>(p);
                    v0 += old.x; v1 += old.y;
                }
                *reinterpret_cast<float2*>(p) = make_float2(v0, v1);
            }
        }
    }
}

// =====================================================================
// FUSED ATTENTION (unchanged)
// =====================================================================
#define KSTR 144
#define PSTR 464
#define SM_Q 0
#define SM_K (SM_Q + 128 * KSTR)
#define SM_V (SM_K + SKP_ * KSTR)
#define SM_P (SM_V + SKP_ * KSTR)
#define ATT_SMEM (SM_P + 128 * PSTR)     // 142336

__global__ __launch_bounds__(256)
void attn_fused(const __half* __restrict__ qh, const __half* __restrict__ kh,
                const __half* __restrict__ vh, __half* __restrict__ o)
{
    extern __shared__ __align__(128) uint8_t sm[];
    __shared__ float red[128][4];

    const int z  = blockIdx.y;
    const int b  = z / H_, h = z % H_;
    const int m0 = blockIdx.x * 128;

    const int t    = threadIdx.x;
    const int warp = t >> 5, lane = t & 31;
    const int wm   = (warp >> 2) * 64;
    const int wn   = (warp & 3) * 56;
    const int wnv  = (warp & 3) * 16;
    const int grp  = lane >> 2;
    const int idx  = lane & 3;
    const int wc   = warp & 3;

    const uint32_t sq = smem_u32(sm) + SM_Q;
    const uint32_t sk = smem_u32(sm) + SM_K;
    const uint32_t sv = smem_u32(sm) + SM_V;
    const uint32_t sp = smem_u32(sm) + SM_P;

    const __half* qbase = qh + ((size_t)b * S_) * W_ + h * HD_;
    const __half* kbase = kh + ((size_t)b * S_) * W_ + h * HD_;
    const __half* vbase = vh + ((size_t)b * S_) * W_ + h * HD_;

    #pragma unroll
    for (int i = 0; i < 4; i++) {
        const int c = t + i * 256;
        const int r = c >> 3, ck = c & 7;
        cp16(sq + r * KSTR + ck * 16, qbase + (size_t)(m0 + r) * W_ + ck * 8,
             (m0 + r) < S_);
    }
    #pragma unroll
    for (int i = 0; i < 7; i++) {
        const int c = t + i * 256;
        const int r = c >> 3, ck = c & 7;
        cp16(sk + r * KSTR + ck * 16, kbase + (size_t)r * W_ + ck * 8, r < S_);
        cp16(sv + r * KSTR + ck * 16, vbase + (size_t)r * W_ + ck * 8, r < S_);
    }
    CP_COMMIT();
    CP_WAIT0();
    __syncthreads();

    float acc[4][7][4];
    #pragma unroll
    for (int a = 0; a < 4; a++)
        #pragma unroll
        for (int n = 0; n < 7; n++)
            #pragma unroll
            for (int c = 0; c < 4; c++) acc[a][n][c] = 0.0f;

    const int aoffq = (wm + (lane & 15)) * KSTR + (lane >> 4) * 16;
    const int boffk = ((lane & 7)) * KSTR + ((lane >> 3) & 1) * 16;

    #pragma unroll
    for (int ks = 0; ks < 4; ks++) {
        uint32_t af[4][4], bf[7][2];
        #pragma unroll
        for (int mt = 0; mt < 4; mt++)
            LDSM_X4(af[mt], sq + aoffq + mt * 16 * KSTR + ks * 32);
        #pragma unroll
        for (int nt = 0; nt < 7; nt++)
            LDSM_X2(bf[nt], sk + boffk + (wn + nt * 8) * KSTR + ks * 32);
        #pragma unroll
        for (int mt = 0; mt < 4; mt++)
            #pragma unroll
            for (int nt = 0; nt < 7; nt++)
                MMA16816(acc[mt][nt], af[mt], bf[nt]);
    }

    #pragma unroll
    for (int mt = 0; mt < 4; mt++)
        #pragma unroll
        for (int nt = 0; nt < 7; nt++)
            #pragma unroll
            for (int c = 0; c < 4; c++) {
                const int col = wn + nt * 8 + idx * 2 + (c & 1);
                acc[mt][nt][c] = (col < S_) ? acc[mt][nt][c] * 0.125f : -1e30f;
            }

    float gmax[4][2], gsum[4][2];

    #pragma unroll
    for (int mt = 0; mt < 4; mt++)
        #pragma unroll
        for (int hf = 0; hf < 2; hf++) {
            float m = -1e30f;
            #pragma unroll
            for (int nt = 0; nt < 7; nt++) {
                m = fmaxf(m, acc[mt][nt][hf * 2 + 0]);
                m = fmaxf(m, acc[mt][nt][hf * 2 + 1]);
            }
            m = fmaxf(m, __shfl_xor_sync(0xffffffffu, m, 1));
            m = fmaxf(m, __shfl_xor_sync(0xffffffffu, m, 2));
            if (idx == 0) red[wm + mt * 16 + hf * 8 + grp][wc] = m;
        }
    __syncthreads();
    #pragma unroll
    for (int mt = 0; mt < 4; mt++)
        #pragma unroll
        for (int hf = 0; hf < 2; hf++) {
            const int row = wm + mt * 16 + hf * 8 + grp;
            gmax[mt][hf] = fmaxf(fmaxf(red[row][0], red[row][1]),
                                 fmaxf(red[row][2], red[row][3]));
        }
    __syncthreads();

    #pragma unroll
    for (int mt = 0; mt < 4; mt++)
        #pragma unroll
        for (int hf = 0; hf < 2; hf++) {
            float s = 0.f;
            #pragma unroll
            for (int nt = 0; nt < 7; nt++) {
                float e0 = expf(acc[mt][nt][hf * 2 + 0] - gmax[mt][hf]);
                float e1 = expf(acc[mt][nt][hf * 2 + 1] - gmax[mt][hf]);
                acc[mt][nt][hf * 2 + 0] = e0;
                acc[mt][nt][hf * 2 + 1] = e1;
                s += e0 + e1;
            }
            s += __shfl_xor_sync(0xffffffffu, s, 1);
            s += __shfl_xor_sync(0xffffffffu, s, 2);
            if (idx == 0) red[wm + mt * 16 + hf * 8 + grp][wc] = s;
        }
    __syncthreads();
    #pragma unroll
    for (int mt = 0; mt < 4; mt++)
        #pragma unroll
        for (int hf = 0; hf < 2; hf++) {
            const int row = wm + mt * 16 + hf * 8 + grp;
            gsum[mt][hf] = red[row][0] + red[row][1] + red[row][2] + red[row][3];
        }

    #pragma unroll
    for (int mt = 0; mt < 4; mt++)
        #pragma unroll
        for (int hf = 0; hf < 2; hf++) {
            const int row = wm + mt * 16 + hf * 8 + grp;
            const float inv = 1.0f / gsum[mt][hf];
            #pragma unroll
            for (int nt = 0; nt < 7; nt++) {
                const int col = wn + nt * 8 + idx * 2;
                *reinterpret_cast<__half2*>(reinterpret_cast<uint8_t*>(sm) + SM_P +
                                            row * PSTR + col * 2) =
                    __floats2half2_rn(acc[mt][nt][hf * 2 + 0] * inv,
                                      acc[mt][nt][hf * 2 + 1] * inv);
            }
        }
    __syncthreads();

    float acc2[4][2][4];
    #pragma unroll
    for (int a = 0; a < 4; a++)
        #pragma unroll
        for (int n = 0; n < 2; n++)
            #pragma unroll
            for (int c = 0; c < 4; c++) acc2[a][n][c] = 0.0f;

    const int aoffp = (wm + (lane & 15)) * PSTR + (lane >> 4) * 16;

    #pragma unroll
    for (int ks = 0; ks < 14; ks++) {
        uint32_t af[4][4], bf[2][2];
        #pragma unroll
        for (int mt = 0; mt < 4; mt++)
            LDSM_X4(af[mt], sp + aoffp + mt * 16 * PSTR + ks * 32);
        #pragma unroll
        for (int nt = 0; nt < 2; nt++)
            LDSM_X2T(bf[nt], sv + (ks * 16 + (lane & 7) + ((lane >> 3) & 1) * 8) * KSTR
                              + (wnv + nt * 8) * 2);
        #pragma unroll
        for (int mt = 0; mt < 4; mt++)
            #pragma unroll
            for (int nt = 0; nt < 2; nt++)
                MMA16816(acc2[mt][nt], af[mt], bf[nt]);
    }

    __half* obase = o + ((size_t)b * S_) * W_ + h * HD_;
    #pragma unroll
    for (int mt = 0; mt < 4; mt++)
        #pragma unroll
        for (int hf = 0; hf < 2; hf++) {
            const int gs = m0 + wm + mt * 16 + hf * 8 + grp;
            if (gs >= S_) continue;
            #pragma unroll
            for (int nt = 0; nt < 2; nt++) {
                const int d = wnv + nt * 8 + idx * 2;
                *reinterpret_cast<__half2*>(obase + (size_t)gs * W_ + d) =
                    __floats2half2_rn(acc2[mt][nt][hf * 2 + 0],
                                      acc2[mt][nt][hf * 2 + 1]);
            }
        }
}

// ---------------- transpose f32->f16, half2 stores (64r x 32c tiles) ----------------
// in [R,Cc] f32 -> out [Cc,R] f16 at layer offset. Requires R % 64 == 0.
__global__ void transpose_h_kernel(const float* __restrict__ in, __half* __restrict__ out,
                                   int R, int Cc, long long ldOut, int rowOff)
{
    __shared__ float tile[32][65];   // [c][r]
    const size_t li = (size_t)blockIdx.z * R * Cc;
    const int c0 = blockIdx.x * 32, r0 = blockIdx.y * 64;
    const int x = threadIdx.x, y = threadIdx.y;   // 32 x 8
    #pragma unroll
    for (int j = 0; j < 64; j += 8)
        tile[x][y + j] = in[li + (size_t)(r0 + y + j) * Cc + c0 + x];
    __syncthreads();
    #pragma unroll
    for (int j = 0; j < 32; j += 8) {
        const int cr = y + j;
        __half2 hv = __floats2half2_rn(tile[cr][2 * x], tile[cr][2 * x + 1]);
        *reinterpret_cast<__half2*>(out + (size_t)blockIdx.z * ldOut +
                                    (size_t)(rowOff + c0 + cr) * R + r0 + 2 * x) = hv;
    }
}

__global__ void convw_h_kernel(const float* __restrict__ in, __half* __restrict__ out)
{
    int i = blockIdx.x * 256 + threadIdx.x;
    if (i < W_ * W_) out[i] = __float2half(in[i]);
}

__global__ void bias_concat_kernel(const float* __restrict__ bq, const float* __restrict__ bk,
                                   const float* __restrict__ bv, float* __restrict__ o)
{
    int i = blockIdx.x * 256 + threadIdx.x;
    if (i >= L_ * QKV_) return;
    const int l = i / QKV_, j = i % QKV_;
    float v = (j < W_) ? bq[l * W_ + j]
            : (j < 2 * W_) ? bk[l * W_ + j - W_]
            : bv[l * W_ + j - 2 * W_];
    o[i] = v;
}

// ---------------- im2col ----------------
__global__ void im2col_kernel(const float* __restrict__ x, __half* __restrict__ out)
{
    const int total = B_ * NPATCH_ * W_;
    int idx = blockIdx.x * 256 + threadIdx.x;
    if (idx >= total) return;
    const int kk = idx % W_;
    const int r  = idx / W_;
    const int b  = r / NPATCH_;
    const int p  = r % NPATCH_;
    const int ph = p / 14, pw = p % 14;
    const int c  = kk >> 8;
    const int py = (kk >> 4) & 15;
    const int px = kk & 15;
    out[idx] = __float2half(
        x[(((size_t)b * C_ + c) * IMG_ + ph * P_ + py) * IMG_ + pw * P_ + px]);
}

// ---------------- assemble ----------------
__global__ void assemble_kernel(const float* __restrict__ tok,
                                const float* __restrict__ cls,
                                const float* __restrict__ pe,
                                float* __restrict__ h)
{
    int idx = blockIdx.x * 256 + threadIdx.x;
    if (idx >= BSW_) return;
    const int w  = idx % W_;
    const int bs = idx / W_;
    const int s  = bs % S_;
    const int b  = bs / S_;
    float v = (s == 0) ? cls[w] : tok[((size_t)b * NPATCH_ + (s - 1)) * W_ + w];
    h[idx] = v + pe[(size_t)s * W_ + w];
}

// ---------------- layernorm: warp-per-row ----------------
__global__ void layernorm_kernel(const float* __restrict__ x,
                                 const float* __restrict__ gamma,
                                 const float* __restrict__ beta,
                                 __half* __restrict__ y, int nrows)
{
    const int warp = threadIdx.x >> 5, lane = threadIdx.x & 31;
    const int row = blockIdx.x * 8 + warp;
    if (row >= nrows) return;

    const float4* xr = reinterpret_cast<const float4*>(x + (size_t)row * W_);
    float4 v[6];
    float s = 0.f, s2 = 0.f;
    #pragma unroll
    for (int i = 0; i < 6; i++) {
        v[i] = xr[lane + 32 * i];
        s  += v[i].x + v[i].y + v[i].z + v[i].w;
        s2 += v[i].x * v[i].x + v[i].y * v[i].y + v[i].z * v[i].z + v[i].w * v[i].w;
    }
    #pragma unroll
    for (int off = 16; off > 0; off >>= 1) {
        s  += __shfl_xor_sync(0xffffffffu, s, off);
        s2 += __shfl_xor_sync(0xffffffffu, s2, off);
    }
    const float mean = s * (1.0f / W_);
    const float inv  = rsqrtf(s2 * (1.0f / W_) - mean * mean + 1e-5f);

    const float4* gp = reinterpret_cast<const float4*>(gamma);
    const float4* bp = reinterpret_cast<const float4*>(beta);
    uint2* yr = reinterpret_cast<uint2*>(y + (size_t)row * W_);
    #pragma unroll
    for (int i = 0; i < 6; i++) {
        const int c4 = lane + 32 * i;
        float4 g = gp[c4], bb = bp[c4];
        float o0 = (v[i].x - mean) * inv * g.x + bb.x;
        float o1 = (v[i].y - mean) * inv * g.y + bb.y;
        float o2 = (v[i].z - mean) * inv * g.z + bb.z;
        float o3 = (v[i].w - mean) * inv * g.w + bb.w;
        __half2 h0 = __floats2half2_rn(o0, o1);
        __half2 h1 = __floats2half2_rn(o2, o3);
        yr[c4] = make_uint2(*reinterpret_cast<uint32_t*>(&h0),
                            *reinterpret_cast<uint32_t*>(&h1));
    }
}

// ---------------- gather / l2norm ----------------
__global__ void gather_cls_kernel(const float* __restrict__ h, __half* __restrict__ cls)
{
    int idx = blockIdx.x * 256 + threadIdx.x;
    if (idx >= B_ * W_) return;
    const int b = idx / W_, w = idx % W_;
    cls[idx] = __float2half(h[(size_t)b * S_ * W_ + w]);
}

__global__ void l2norm_kernel(float* __restrict__ out)
{
    const int row = blockIdx.x;
    float* r = out + (size_t)row * E_;
    float s = 0.f;
    for (int i = threadIdx.x; i < E_; i += 256) { float v = r[i]; s += v * v; }
    for (int off = 16; off > 0; off >>= 1) s += __shfl_down_sync(0xffffffffu, s, off);
    __shared__ float rs[8];
    const int warp = threadIdx.x >> 5, lane = threadIdx.x & 31;
    if (lane == 0) rs[warp] = s;
    __syncthreads();
    __shared__ float inv_sh;
    if (threadIdx.x == 0) {
        float ts = 0.f;
        for (int i = 0; i < 8; i++) ts += rs[i];
        inv_sh = rsqrtf(ts);
    }
    __syncthreads();
    const float inv = inv_sh;
    for (int i = threadIdx.x; i < E_; i += 256) r[i] *= inv;
}

// ---------------- launch ----------------
extern "C" void kernel_launch(void* const* d_in, const int* in_sizes, int n_in,
                              void* d_out, int out_size)
{
    (void)in_sizes; (void)n_in; (void)out_size;

    const float* x       = (const float*)d_in[0];
    const float* conv_w  = (const float*)d_in[1];
    const float* conv_b  = (const float*)d_in[2];
    const float* cls_tok = (const float*)d_in[3];
    const float* pe      = (const float*)d_in[4];
    const float* ln1_g   = (const float*)d_in[5];
    const float* ln1_b   = (const float*)d_in[6];
    const float* wq      = (const float*)d_in[7];
    const float* bq      = (const float*)d_in[8];
    const float* wk      = (const float*)d_in[9];
    const float* bk      = (const float*)d_in[10];
    const float* wv      = (const float*)d_in[11];
    const float* bv      = (const float*)d_in[12];
    const float* wo      = (const float*)d_in[13];
    const float* bo      = (const float*)d_in[14];
    const float* ln2_g   = (const float*)d_in[15];
    const float* ln2_b   = (const float*)d_in[16];
    const float* w1      = (const float*)d_in[17];
    const float* b1      = (const float*)d_in[18];
    const float* w2      = (const float*)d_in[19];
    const float* b2      = (const float*)d_in[20];
    const float* proj    = (const float*)d_in[21];
    float* out           = (float*)d_out;

    float  *h, *tok, *bqkv;
    __half *y, *qh, *kh, *vh, *o, *ff, *i2c, *cls, *convw16;
    __half *wqkvT, *woT, *w1T, *w2T, *projT;
    cudaGetSymbolAddress((void**)&h,    g_h);
    cudaGetSymbolAddress((void**)&y,    g_y);
    cudaGetSymbolAddress((void**)&qh,   g_qh);
    cudaGetSymbolAddress((void**)&kh,   g_kh);
    cudaGetSymbolAddress((void**)&vh,   g_vh);
    cudaGetSymbolAddress((void**)&o,    g_o);
    cudaGetSymbolAddress((void**)&ff,   g_ff);
    cudaGetSymbolAddress((void**)&i2c,  g_im2col);
    cudaGetSymbolAddress((void**)&tok,  g_tok);
    cudaGetSymbolAddress((void**)&cls,  g_cls);
    cudaGetSymbolAddress((void**)&convw16, g_convw16);
    cudaGetSymbolAddress((void**)&wqkvT, g_wqkvT);
    cudaGetSymbolAddress((void**)&bqkv,  g_bqkv);
    cudaGetSymbolAddress((void**)&woT,  g_woT);
    cudaGetSymbolAddress((void**)&w1T,  g_w1T);
    cudaGetSymbolAddress((void**)&w2T,  g_w2T);
    cudaGetSymbolAddress((void**)&projT, g_projT);

    cudaFuncSetAttribute(gemm_wide<1,0,0,0>, cudaFuncAttributeMaxDynamicSharedMemorySize, WSMEM);
    cudaFuncSetAttribute(gemm_wide<1,0,0,3>, cudaFuncAttributeMaxDynamicSharedMemorySize, WSMEM);
    cudaFuncSetAttribute(gemm_wide<0,0,0,0>, cudaFuncAttributeMaxDynamicSharedMemorySize, WSMEM);
    cudaFuncSetAttribute(gemm_wide<1,0,1,1>, cudaFuncAttributeMaxDynamicSharedMemorySize, WSMEM);
    cudaFuncSetAttribute(gemm_n<1,1>, cudaFuncAttributeMaxDynamicSharedMemorySize, NSMEM);
    cudaFuncSetAttribute(attn_fused, cudaFuncAttributeMaxDynamicSharedMemorySize, ATT_SMEM);

    const int M  = B_ * S_;       // 6304
    const int Mp = B_ * NPATCH_;  // 6272
    dim3 blkT(32, 8);

    im2col_kernel<<<(Mp * W_ + 255) / 256, 256>>>(x, i2c);
    convw_h_kernel<<<(W_ * W_ + 255) / 256, 256>>>(conv_w, convw16);
    // transposes: grid (Cc/32, R/64, layers)
    transpose_h_kernel<<<dim3(W_/32, W_/64, L_), blkT>>>(wq, wqkvT, W_, W_, (long long)QKV_*W_, 0);
    transpose_h_kernel<<<dim3(W_/32, W_/64, L_), blkT>>>(wk, wqkvT, W_, W_, (long long)QKV_*W_, W_);
    transpose_h_kernel<<<dim3(W_/32, W_/64, L_), blkT>>>(wv, wqkvT, W_, W_, (long long)QKV_*W_, 2*W_);
    bias_concat_kernel<<<(L_*QKV_ + 255) / 256, 256>>>(bq, bk, bv, bqkv);
    transpose_h_kernel<<<dim3(W_/32,  W_/64,  L_), blkT>>>(wo, woT, W_, W_, (long long)W_*W_, 0);
    transpose_h_kernel<<<dim3(FF_/32, W_/64,  L_), blkT>>>(w1, w1T, W_, FF_, (long long)W_*FF_, 0);
    transpose_h_kernel<<<dim3(W_/32,  FF_/64, L_), blkT>>>(w2, w2T, FF_, W_, (long long)FF_*W_, 0);
    transpose_h_kernel<<<dim3(E_/32,  W_/64,  1),  blkT>>>(proj, projT, W_, E_, (long long)W_*E_, 0);

    {   // patch embed GEMM -> tok (f32)
        dim3 grid(3, (Mp + 127) / 128, 1);
        gemm_wide<1,0,0,0><<<grid, 512, WSMEM>>>(i2c, convw16, conv_b, tok,
            nullptr, nullptr, nullptr, Mp, W_, W_, W_, W_, W_);
    }
    assemble_kernel<<<(BSW_ + 255) / 256, 256>>>(tok, cls_tok, pe, h);

    dim3 gridQKV(QKV_ / 256, (M + 127) / 128, 1);
    dim3 gridN  (W_ / 128, (M + 127) / 128, 1);
    dim3 gridFF (FF_ / 256, (M + 127) / 128, 1);
    dim3 gridAtt(2, B_ * H_, 1);
    const int lnGrid = (M + 7) / 8;

    for (int l = 0; l < L_; l++) {
        const size_t bOff = (size_t)l * W_;

        layernorm_kernel<<<lnGrid, 256>>>(h, ln1_g + bOff, ln1_b + bOff, y, M);
        gemm_wide<1,0,0,3><<<gridQKV, 512, WSMEM>>>(y, wqkvT + (size_t)l * QKV_ * W_,
            bqkv + (size_t)l * QKV_, nullptr, qh, kh, vh,
            M, QKV_, W_, W_, W_, 0);
        attn_fused<<<gridAtt, 256, ATT_SMEM>>>(qh, kh, vh, o);
        gemm_n<1,1><<<gridN, 256, NSMEM>>>(o, woT + (size_t)l * W_ * W_,
            bo + bOff, h, M, W_, W_, W_, W_, W_);
        layernorm_kernel<<<lnGrid, 256>>>(h, ln2_g + bOff, ln2_b + bOff, y, M);
        gemm_wide<1,0,1,1><<<gridFF, 512, WSMEM>>>(y, w1T + (size_t)l * W_ * FF_,
            b1 + (size_t)l * FF_, nullptr, ff, nullptr, nullptr,
            M, FF_, W_, W_, W_, FF_);
        gemm_n<1,1><<<gridN, 256, NSMEM>>>(ff, w2T + (size_t)l * FF_ * W_,
            b2 + bOff, h, M, W_, FF_, FF_, FF_, W_);
    }

    gather_cls_kernel<<<(B_ * W_ + 255) / 256, 256>>>(h, cls);
    {
        dim3 grid(2, 1, 1);
        gemm_wide<0,0,0,0><<<grid, 512, WSMEM>>>(cls, projT, nullptr, out,
            nullptr, nullptr, nullptr, B_, E_, W_, W_, W_, E_);
    }
    l2norm_kernel<<<B_, 256>>>(out);
}